// round 3
// baseline (speedup 1.0000x reference)
#include <cuda_runtime.h>
#include <cuda_bf16.h>
#include <math.h>

// Problem shape (fixed by the reference): x[4,4096,4096] fp32, gate_w[64,4096] fp32
// M = B*S = 16384 tokens, H = 4096, E = 64 experts, K(top) = 2.
// Output (assumed fp32, concatenated in reference return order):
//   [0      , 32768) : topk_idx   as float
//   [32768  , 65536) : topk_scores
//   [65536]          : aux_loss (= 0)
//   [65537]          : z_loss   (= mean(logits^2))

#define M_TOT   16384
#define H_DIM   4096
#define E_NUM   64
#define M_TILE  64
#define KT      32
#define PAD     68          // row stride in floats: 16B-aligned, bank-conflict-free
#define NBLOCKS (M_TOT / M_TILE)   // 256

__device__ float g_partials[NBLOCKS];

__global__ __launch_bounds__(256) void router_main(
    const float* __restrict__ x,
    const float* __restrict__ w,
    float* __restrict__ out)
{
    __shared__ float smem[2 * KT * PAD];   // 4352 floats = 17408 B
    float* xs = smem;                      // [KT][PAD] : xs[k][token]
    float* ws = smem + KT * PAD;           // [KT][PAD] : ws[k][expert]

    const int tid  = threadIdx.x;
    const int tx   = tid & 15;             // expert quad
    const int ty   = tid >> 4;             // token quad
    const int m0   = blockIdx.x * M_TILE;

    float acc[4][4] = {};

    for (int k0 = 0; k0 < H_DIM; k0 += KT) {
        __syncthreads();   // previous compute must finish reading smem
        #pragma unroll
        for (int i = 0; i < 2; i++) {
            int idx = tid + i * 256;       // 0..511
            int row = idx >> 3;            // 0..63
            int kq  = idx & 7;             // float4 slot within KT
            float4 vx = *(const float4*)&x[(size_t)(m0 + row) * H_DIM + k0 + kq * 4];
            xs[(kq * 4 + 0) * PAD + row] = vx.x;
            xs[(kq * 4 + 1) * PAD + row] = vx.y;
            xs[(kq * 4 + 2) * PAD + row] = vx.z;
            xs[(kq * 4 + 3) * PAD + row] = vx.w;
            float4 vw = *(const float4*)&w[(size_t)row * H_DIM + k0 + kq * 4];
            ws[(kq * 4 + 0) * PAD + row] = vw.x;
            ws[(kq * 4 + 1) * PAD + row] = vw.y;
            ws[(kq * 4 + 2) * PAD + row] = vw.z;
            ws[(kq * 4 + 3) * PAD + row] = vw.w;
        }
        __syncthreads();

        #pragma unroll
        for (int kk = 0; kk < KT; kk++) {
            float a[4], b[4];
            *(float4*)a = *(const float4*)&xs[kk * PAD + ty * 4];
            *(float4*)b = *(const float4*)&ws[kk * PAD + tx * 4];
            #pragma unroll
            for (int i = 0; i < 4; i++)
                #pragma unroll
                for (int j = 0; j < 4; j++)
                    acc[i][j] = fmaf(a[i], b[j], acc[i][j]);
        }
    }

    // ---- stage logits tile [64 tokens][64 experts] into smem (reuse) ----
    __syncthreads();
    float* ls = smem;                      // [64][PAD]
    #pragma unroll
    for (int i = 0; i < 4; i++) {
        float4 v = make_float4(acc[i][0], acc[i][1], acc[i][2], acc[i][3]);
        *(float4*)&ls[(ty * 4 + i) * PAD + tx * 4] = v;
    }
    __syncthreads();

    // ---- epilogue: one warp handles 8 tokens ----
    const int warp = tid >> 5;
    const int lane = tid & 31;
    float zacc = 0.f;

    for (int t = warp; t < M_TILE; t += 8) {
        float v0 = ls[t * PAD + lane];
        float v1 = ls[t * PAD + lane + 32];
        zacc += v0 * v0 + v1 * v1;

        // local top-2 (tie -> lower index, matching lax.top_k)
        float m1, m2; int i1, i2;
        if (v0 >= v1) { m1 = v0; i1 = lane;      m2 = v1; i2 = lane + 32; }
        else          { m1 = v1; i1 = lane + 32; m2 = v0; i2 = lane;      }

        #pragma unroll
        for (int off = 16; off > 0; off >>= 1) {
            float bm1 = __shfl_xor_sync(0xffffffffu, m1, off);
            float bm2 = __shfl_xor_sync(0xffffffffu, m2, off);
            int   bi1 = __shfl_xor_sync(0xffffffffu, i1, off);
            int   bi2 = __shfl_xor_sync(0xffffffffu, i2, off);
            if (bm1 > m1 || (bm1 == m1 && bi1 < i1)) {
                // partner top becomes top; second = best of (our old top, partner second)
                float nm2; int ni2;
                if (m1 > bm2 || (m1 == bm2 && i1 < bi2)) { nm2 = m1;  ni2 = i1;  }
                else                                     { nm2 = bm2; ni2 = bi2; }
                m1 = bm1; i1 = bi1; m2 = nm2; i2 = ni2;
            } else {
                if (bm1 > m2 || (bm1 == m2 && bi1 < i2)) { m2 = bm1; i2 = bi1; }
            }
        }

        // softmax denominator sum of exp(v - max)
        float s = expf(v0 - m1) + expf(v1 - m1);
        #pragma unroll
        for (int off = 16; off > 0; off >>= 1)
            s += __shfl_xor_sync(0xffffffffu, s, off);

        if (lane == 0) {
            int tok = m0 + t;
            out[tok * 2 + 0]                 = (float)i1;
            out[tok * 2 + 1]                 = (float)i2;
            out[M_TOT * 2 + tok * 2 + 0]     = 1.0f / s;            // exp(m1-m1)/s
            out[M_TOT * 2 + tok * 2 + 1]     = expf(m2 - m1) / s;
        }
    }

    // ---- z_loss partial: deterministic per-block sum ----
    #pragma unroll
    for (int off = 16; off > 0; off >>= 1)
        zacc += __shfl_xor_sync(0xffffffffu, zacc, off);

    __shared__ float zsh[8];
    if (lane == 0) zsh[warp] = zacc;
    __syncthreads();
    if (tid == 0) {
        float s = 0.f;
        #pragma unroll
        for (int i = 0; i < 8; i++) s += zsh[i];
        g_partials[blockIdx.x] = s;
    }
}

__global__ __launch_bounds__(256) void router_finalize(float* __restrict__ out)
{
    __shared__ float sh[256];
    int tid = threadIdx.x;
    sh[tid] = g_partials[tid];             // NBLOCKS == 256 exactly
    __syncthreads();
    #pragma unroll
    for (int s = 128; s > 0; s >>= 1) {
        if (tid < s) sh[tid] += sh[tid + s];
        __syncthreads();
    }
    if (tid == 0) {
        out[M_TOT * 4 + 0] = 0.0f;                                  // aux_loss
        out[M_TOT * 4 + 1] = sh[0] / ((float)M_TOT * (float)E_NUM); // z_loss
    }
}

extern "C" void kernel_launch(void* const* d_in, const int* in_sizes, int n_in,
                              void* d_out, int out_size)
{
    const float* x = (const float*)d_in[0];      // [4,4096,4096]
    const float* w = (const float*)d_in[1];      // [64,4096]
    float* out = (float*)d_out;
    router_main<<<NBLOCKS, 256>>>(x, w, out);
    router_finalize<<<1, 256>>>(out);
}